// round 1
// baseline (speedup 1.0000x reference)
#include <cuda_runtime.h>
#include <math.h>

#define BATCH 4
#define CDIM  64
#define KD    32
#define OD    64
#define NPIX  4096
#define KK    409          /* NPIX / TOPK, TOPK=10 -> 4096//10 = 409 */
#define ROWS  8
#define EPSF  1e-10f
#define LISTCAP 512

// ---------------- scratch (device globals: allocation-free) ----------------
__device__ __align__(16) float g_q[BATCH * KD * NPIX];   // [b][kd][n]
__device__ __align__(16) float g_k[BATCH * KD * NPIX];   // [b][kd][n]
__device__ __align__(16) float g_v[BATCH * NPIX * OD];   // [b][n][od]  (column-contiguous)

// ---------------- kernel 0: fused QKV projection ----------------
// grid: BATCH*32 CTAs (128 pixels each), 256 threads
// dynamic smem: xs[64][128] + Wall[128][64] + ball[128]
__global__ void proj_kernel(const float* __restrict__ x,
                            const float* __restrict__ Wq, const float* __restrict__ bq,
                            const float* __restrict__ Wk, const float* __restrict__ bk,
                            const float* __restrict__ Wv, const float* __restrict__ bv)
{
    extern __shared__ float sm[];
    float* xs   = sm;                 // [64][128]
    float* Wall = xs + 64 * 128;      // [128][64]  rows 0-31 Wq, 32-63 Wk, 64-127 Wv
    float* ball = Wall + 128 * 64;    // [128]

    const int b  = blockIdx.x >> 5;
    const int n0 = (blockIdx.x & 31) * 128;
    const int t  = threadIdx.x;

    for (int i = t; i < 32 * 64; i += 256) Wall[i] = Wq[i];
    for (int i = t; i < 32 * 64; i += 256) Wall[32 * 64 + i] = Wk[i];
    for (int i = t; i < 64 * 64; i += 256) Wall[64 * 64 + i] = Wv[i];
    if (t < 32)        ball[t] = bq[t];
    else if (t < 64)   ball[t] = bk[t - 32];
    else if (t < 128)  ball[t] = bv[t - 64];

    const float* xb = x + (size_t)b * CDIM * NPIX;
    for (int i = t; i < CDIM * 128; i += 256) {
        int c = i >> 7, p = i & 127;
        xs[c * 128 + p] = xb[(size_t)c * NPIX + n0 + p];
    }
    __syncthreads();

    const int p = t & 127;
    const int h = t >> 7;

    if (h == 0) {
        // q (oo 0..31) and k (oo 32..63), layout [b][kd][n] -> coalesced across p
        for (int oo = 0; oo < 64; oo++) {
            float acc = ball[oo];
            const float* wr = Wall + oo * 64;
            #pragma unroll 16
            for (int c = 0; c < 64; c++) acc = fmaf(wr[c], xs[c * 128 + p], acc);
            if (oo < 32) g_q[((size_t)b * KD + oo) * NPIX + n0 + p] = acc;
            else         g_k[((size_t)b * KD + (oo - 32)) * NPIX + n0 + p] = acc;
        }
    } else {
        // v: 64 accumulators, then vectorized 16x float4 stores (column-contiguous)
        float vacc[64];
        #pragma unroll
        for (int od = 0; od < 64; od++) vacc[od] = ball[64 + od];
        for (int c = 0; c < 64; c++) {
            float xv = xs[c * 128 + p];
            const float* wr = Wall + (64) * 64 + c;   // Wall[64+od][c] = Wall[(64+od)*64+c]
            #pragma unroll
            for (int od = 0; od < 64; od++) vacc[od] = fmaf(Wall[(64 + od) * 64 + c], xv, vacc[od]);
            (void)wr;
        }
        float4* vd = (float4*)(g_v + ((size_t)b * NPIX + n0 + p) * OD);
        #pragma unroll
        for (int q4 = 0; q4 < 16; q4++)
            vd[q4] = make_float4(vacc[4 * q4], vacc[4 * q4 + 1], vacc[4 * q4 + 2], vacc[4 * q4 + 3]);
    }
}

// ---------------- kernel 1: fused energy + exact top-k threshold + masked softmax + PV ----------------
// grid: BATCH * (NPIX/ROWS) = 2048 CTAs, 512 threads (2 warps per row)
__device__ __forceinline__ unsigned f2mono(float f) {
    unsigned u = __float_as_uint(f);
    return (u & 0x80000000u) ? ~u : (u | 0x80000000u);
}

__global__ void __launch_bounds__(512, 1)
attn_kernel(const float* __restrict__ x, const float* __restrict__ gamma,
            float* __restrict__ out)
{
    extern __shared__ float sm[];
    float*    e      = sm;                                   // [ROWS][NPIX]
    float*    wl     = e + ROWS * NPIX;                      // [ROWS][LISTCAP]
    int*      il     = (int*)(wl + ROWS * LISTCAP);          // [ROWS][LISTCAP]
    int*      hist   = il + ROWS * LISTCAP;                  // [ROWS][256]
    float*    outbuf = (float*)(hist + ROWS * 256);          // [ROWS][OD]
    float*    rowmax = outbuf + ROWS * OD;                   // [ROWS]
    float*    zsum   = rowmax + ROWS;                        // [ROWS]
    float*    wmax   = zsum + ROWS;                          // [16]
    unsigned* prefx  = (unsigned*)(wmax + 16);               // [ROWS]
    int*      remain = (int*)(prefx + ROWS);                 // [ROWS]
    int*      cnt    = remain + ROWS;                        // [ROWS]

    const int b  = blockIdx.x >> 9;                // / (NPIX/ROWS)=512
    const int i0 = (blockIdx.x & 511) * ROWS;
    const int t    = threadIdx.x;
    const int warp = t >> 5, lane = t & 31;
    const int r = warp >> 1, s = warp & 1;
    const int t64 = (s << 5) | lane;               // 0..63 within row group

    if (t < ROWS) { cnt[t] = 0; zsum[t] = 0.f; }

    // ---- load q row into registers (broadcast loads) ----
    float qreg[KD];
    const float* qb = g_q + (size_t)b * KD * NPIX + i0 + r;
    #pragma unroll
    for (int kd = 0; kd < KD; kd++) qreg[kd] = qb[(size_t)kd * NPIX];

    // ---- phase E: energy row + running max ----
    const float4* k4 = (const float4*)(g_k + (size_t)b * KD * NPIX);
    float* erow = e + r * NPIX;
    float lmax = -1e30f;
    for (int jb = s * 128; jb < NPIX; jb += 256) {
        int j4 = (jb >> 2) + lane;
        float4 acc = make_float4(0.f, 0.f, 0.f, 0.f);
        #pragma unroll
        for (int kd = 0; kd < KD; kd++) {
            float4 kv = k4[kd * (NPIX / 4) + j4];
            float  qv = qreg[kd];
            acc.x = fmaf(qv, kv.x, acc.x);
            acc.y = fmaf(qv, kv.y, acc.y);
            acc.z = fmaf(qv, kv.z, acc.z);
            acc.w = fmaf(qv, kv.w, acc.w);
        }
        ((float4*)erow)[j4] = acc;
        lmax = fmaxf(lmax, fmaxf(fmaxf(acc.x, acc.y), fmaxf(acc.z, acc.w)));
    }
    #pragma unroll
    for (int o = 16; o; o >>= 1) lmax = fmaxf(lmax, __shfl_xor_sync(0xffffffffu, lmax, o));
    if (lane == 0) wmax[warp] = lmax;
    __syncthreads();
    if (t < ROWS) rowmax[t] = fmaxf(wmax[2 * t], wmax[2 * t + 1]);
    __syncthreads();

    // ---- phase T: exact radix select of 409th largest (4 passes of 8 bits, MSB first) ----
    unsigned pfx = 0;
    int rem = KK;
    int* h = hist + r * 256;
    for (int pass = 0; pass < 4; pass++) {
        for (int i = t64; i < 256; i += 64) h[i] = 0;
        __syncthreads();
        const int shift = 24 - 8 * pass;
        for (int j = t64; j < NPIX; j += 64) {
            unsigned u = f2mono(erow[j]);
            bool match = (pass == 0) ? true : ((u >> (shift + 8)) == pfx);
            if (match) atomicAdd(&h[(u >> shift) & 255], 1);
        }
        __syncthreads();
        if (t64 == 0) {
            int cum = 0, bsel = 0;
            for (int bb = 255; bb >= 0; bb--) {
                int c = h[bb];
                if (cum + c >= rem) { bsel = bb; break; }
                cum += c;
            }
            prefx[r]  = (pfx << 8) | (unsigned)bsel;
            remain[r] = rem - cum;
        }
        __syncthreads();
        pfx = prefx[r];
        rem = remain[r];
    }
    const unsigned Tu = pfx;   // exact bits of the KK-th largest energy in this row

    // ---- phase W: mask + exp + compact (index,weight) list; row sum Z ----
    const float m = rowmax[r];
    float zpart = 0.f;
    for (int j = t64; j < NPIX; j += 64) {
        float ev = erow[j];
        if (f2mono(ev) >= Tu) {
            float w = __expf(ev - m);
            zpart += w;
            int pos = atomicAdd(&cnt[r], 1);
            if (pos < LISTCAP) {
                il[r * LISTCAP + pos] = j;
                wl[r * LISTCAP + pos] = w;
            }
        }
    }
    #pragma unroll
    for (int o = 16; o; o >>= 1) zpart += __shfl_xor_sync(0xffffffffu, zpart, o);
    if (lane == 0) atomicAdd(&zsum[r], zpart);
    __syncthreads();

    // ---- phase PV: sparse gather of selected v columns ----
    int n = cnt[r]; if (n > LISTCAP) n = LISTCAP;
    const float* vb = g_v + (size_t)b * NPIX * OD;
    float2 o2 = make_float2(0.f, 0.f);
    for (int tix = s; tix < n; tix += 2) {
        int   j = il[r * LISTCAP + tix];
        float w = wl[r * LISTCAP + tix];
        float2 vv = ((const float2*)(vb + (size_t)j * OD))[lane];
        o2.x = fmaf(w, vv.x, o2.x);
        o2.y = fmaf(w, vv.y, o2.y);
    }
    float* ob = outbuf + r * OD;
    if (s == 0) ((float2*)ob)[lane] = o2;
    __syncthreads();
    if (s == 1) {
        float2 prev = ((float2*)ob)[lane];
        prev.x += o2.x; prev.y += o2.y;
        ((float2*)ob)[lane] = prev;
    }
    __syncthreads();

    // ---- epilogue: normalize, scale by gamma, add residual, write ----
    const float g = gamma[0];
    const int r2 = t & 7, c = t >> 3;                 // 512 threads = 8 rows x 64 channels
    const float invZ = 1.f / (zsum[r2] + EPSF);
    const size_t oix = ((size_t)b * CDIM + c) * NPIX + i0 + r2;
    out[oix] = g * outbuf[r2 * OD + c] * invZ + x[oix];
}

// ---------------- launch ----------------
extern "C" void kernel_launch(void* const* d_in, const int* in_sizes, int n_in,
                              void* d_out, int out_size)
{
    const float* x     = (const float*)d_in[0];
    const float* Wq    = (const float*)d_in[1];
    const float* bq    = (const float*)d_in[2];
    const float* Wk    = (const float*)d_in[3];
    const float* bk    = (const float*)d_in[4];
    const float* Wv    = (const float*)d_in[5];
    const float* bv    = (const float*)d_in[6];
    const float* gamma = (const float*)d_in[7];
    float* out = (float*)d_out;

    (void)in_sizes; (void)n_in; (void)out_size;

    const int SMEM_PROJ = (64 * 128 + 128 * 64 + 128) * 4;                        // 66048 B
    const int SMEM_ATTN = (ROWS * NPIX + ROWS * LISTCAP) * 4 +                    // e + wl
                          (ROWS * LISTCAP + ROWS * 256) * 4 +                     // il + hist
                          (ROWS * OD + ROWS + ROWS + 16) * 4 +                    // outbuf+rowmax+zsum+wmax
                          (ROWS + ROWS + ROWS) * 4;                               // prefx+remain+cnt

    cudaFuncSetAttribute(proj_kernel, cudaFuncAttributeMaxDynamicSharedMemorySize, SMEM_PROJ);
    cudaFuncSetAttribute(attn_kernel, cudaFuncAttributeMaxDynamicSharedMemorySize, SMEM_ATTN);

    proj_kernel<<<BATCH * 32, 256, SMEM_PROJ>>>(x, Wq, bq, Wk, bk, Wv, bv);
    attn_kernel<<<BATCH * (NPIX / ROWS), 512, SMEM_ATTN>>>(x, gamma, out);
}